// round 13
// baseline (speedup 1.0000x reference)
#include <cuda_runtime.h>
#include <cuda_fp16.h>
#include <cstdint>

#define ND 20000
#define NP 20000
#define NN 20000
#define FH 512
#define FF (FH * FH)
#define EE 320000

// ---------------- device scratch (static, no allocation) ----------------
__device__ float g_Da[ND * FH], g_Pa[NP * FH];
__device__ __align__(16) __half g_Xdh[ND * FH];
__device__ __align__(16) __half g_Xph[NP * FH];
__device__ __align__(16) __half g_Mh[4][NN * FH];
__device__ __align__(16) __half g_Wth[6][FF];
__device__ float g_bsum[FH], g_scale[2 * FH], g_shift[2 * FH];
__device__ float g_psum[2 * FH], g_psq[2 * FH];
__device__ int g_off[4 * (NN + 1)], g_cur[4 * (NN + 1)], g_val[4 * EE];

// ---------------- helpers ----------------
__device__ __forceinline__ uint32_t smem_u32(const void* p) {
    uint32_t a;
    asm("{ .reg .u64 t; cvta.to.shared.u64 t, %1; cvt.u32.u64 %0, t; }" : "=r"(a) : "l"(p));
    return a;
}

#define LDSM4(r, addr) \
    asm volatile("ldmatrix.sync.aligned.m8n8.x4.shared.b16 {%0,%1,%2,%3}, [%4];" \
                 : "=r"((r)[0]), "=r"((r)[1]), "=r"((r)[2]), "=r"((r)[3]) : "r"(addr))

#define MMA16816(c, a, b0, b1) \
    asm volatile("mma.sync.aligned.m16n8k16.row.col.f32.f16.f16.f32 " \
                 "{%0,%1,%2,%3}, {%4,%5,%6,%7}, {%8,%9}, {%0,%1,%2,%3};" \
                 : "+f"((c)[0]), "+f"((c)[1]), "+f"((c)[2]), "+f"((c)[3]) \
                 : "r"((a)[0]), "r"((a)[1]), "r"((a)[2]), "r"((a)[3]), "r"(b0), "r"(b1))

#define CP_ASYNC16(dst, src, sz) \
    asm volatile("cp.async.cg.shared.global [%0], [%1], 16, %2;" :: "r"(dst), "l"(src), "r"(sz) : "memory")
#define CP_COMMIT() asm volatile("cp.async.commit_group;" ::: "memory")
#define CP_WAIT1() asm volatile("cp.async.wait_group 1;" ::: "memory")

// ---------------- CSR build ----------------
__global__ void hist_kernel(const int* __restrict__ grp, int* __restrict__ off, int E) {
    int e = blockIdx.x * blockDim.x + threadIdx.x;
    if (e < E) atomicAdd(&off[grp[e] + 1], 1);
}
__global__ void scan_kernel(int* __restrict__ off, int n) {
    __shared__ int ssum[1024];
    const int T = 1024;
    int t = threadIdx.x;
    int chunk = (n + T - 1) / T;
    int lo = 1 + t * chunk;
    int hi = lo + chunk;
    if (hi > n + 1) hi = n + 1;
    int s = 0;
    for (int i = lo; i < hi && i <= n; i++) s += off[i];
    ssum[t] = s;
    __syncthreads();
    for (int d = 1; d < T; d <<= 1) {
        int v = (t >= d) ? ssum[t - d] : 0;
        __syncthreads();
        ssum[t] += v;
        __syncthreads();
    }
    int run = (t > 0) ? ssum[t - 1] : 0;
    for (int i = lo; i < hi && i <= n; i++) {
        run += off[i];
        off[i] = run;
    }
}
__global__ void fill_kernel(const int* __restrict__ grp, const int* __restrict__ oth,
                            int* __restrict__ cur, int* __restrict__ val, int E) {
    int e = blockIdx.x * blockDim.x + threadIdx.x;
    if (e < E) {
        int p = atomicAdd(&cur[grp[e]], 1);
        val[p] = oth[e];
    }
}

// ---------------- fused 4-relation segment mean (fp16, MLP-unrolled) ----------------
struct SegArgs {
    const __half* X[4];
    const int* off[4];
    const int* val[4];
    __half* out[4];
};
__global__ void seg_mean4(SegArgs args) {
    int rel = blockIdx.y;
    const __half* X = args.X[rel];
    const int* off = args.off[rel];
    const int* val = args.val[rel];
    __half* out = args.out[rel];
    int c = threadIdx.x * 4;  // 128 threads * 4 halves = 512
    for (int d = blockIdx.x; d < NN; d += gridDim.x) {
        int s = off[d], e = off[d + 1];
        float a0 = 0.f, a1 = 0.f, a2 = 0.f, a3 = 0.f;
        int j = s;
        for (; j + 4 <= e; j += 4) {
            int n0 = __ldg(&val[j]);
            int n1 = __ldg(&val[j + 1]);
            int n2 = __ldg(&val[j + 2]);
            int n3 = __ldg(&val[j + 3]);
            uint2 v0 = *(const uint2*)(X + (size_t)n0 * FH + c);
            uint2 v1 = *(const uint2*)(X + (size_t)n1 * FH + c);
            uint2 v2 = *(const uint2*)(X + (size_t)n2 * FH + c);
            uint2 v3 = *(const uint2*)(X + (size_t)n3 * FH + c);
            float2 f;
            f = __half22float2(*(const __half2*)&v0.x); a0 += f.x; a1 += f.y;
            f = __half22float2(*(const __half2*)&v0.y); a2 += f.x; a3 += f.y;
            f = __half22float2(*(const __half2*)&v1.x); a0 += f.x; a1 += f.y;
            f = __half22float2(*(const __half2*)&v1.y); a2 += f.x; a3 += f.y;
            f = __half22float2(*(const __half2*)&v2.x); a0 += f.x; a1 += f.y;
            f = __half22float2(*(const __half2*)&v2.y); a2 += f.x; a3 += f.y;
            f = __half22float2(*(const __half2*)&v3.x); a0 += f.x; a1 += f.y;
            f = __half22float2(*(const __half2*)&v3.y); a2 += f.x; a3 += f.y;
        }
        for (; j < e; j++) {
            int nb = __ldg(&val[j]);
            uint2 v = *(const uint2*)(X + (size_t)nb * FH + c);
            float2 f0 = __half22float2(*(const __half2*)&v.x);
            float2 f1 = __half22float2(*(const __half2*)&v.y);
            a0 += f0.x; a1 += f0.y; a2 += f1.x; a3 += f1.y;
        }
        int deg = e - s;
        float inv = 1.0f / (float)(deg > 0 ? deg : 1);
        __half2 o0 = __floats2half2_rn(a0 * inv, a1 * inv);
        __half2 o1 = __floats2half2_rn(a2 * inv, a3 * inv);
        uint2 ov;
        ov.x = *(const uint32_t*)&o0;
        ov.y = *(const uint32_t*)&o1;
        *(uint2*)(out + (size_t)d * FH + c) = ov;
    }
}

// ---------------- fp32 -> fp16 ----------------
__global__ void cvt_half(const float* __restrict__ X, __half* __restrict__ H, int n4) {
    int i = blockIdx.x * blockDim.x + threadIdx.x;
    if (i >= n4) return;
    float4 x = ((const float4*)X)[i];
    __half2 h0 = __floats2half2_rn(x.x, x.y);
    __half2 h1 = __floats2half2_rn(x.z, x.w);
    uint2 v;
    v.x = *(const uint32_t*)&h0;
    v.y = *(const uint32_t*)&h1;
    ((uint2*)H)[i] = v;
}

// ---------------- fused 6-way weight transpose (+fold for z=2): W[K,N] -> T[N,K] fp16 ----
__global__ void wtrans6(const float* __restrict__ Ws, const float* __restrict__ Wn,
                        __half* __restrict__ dstB) {
    __shared__ float t[32][33];
    int z = blockIdx.z;
    int k = blockIdx.y * 32 + threadIdx.y;
    int n = blockIdx.x * 32 + threadIdx.x;
    size_t idx = (size_t)k * FH + n;
    float v;
    switch (z) {
        case 0: v = Ws[FF + idx]; break;
        case 1: v = Wn[FF + idx]; break;
        case 2: v = Ws[idx] + Ws[2 * FF + idx] + Ws[3 * FF + idx]; break;
        case 3: v = Wn[idx]; break;
        case 4: v = Wn[2 * FF + idx]; break;
        default: v = Wn[3 * FF + idx]; break;
    }
    t[threadIdx.y][threadIdx.x] = v;
    __syncthreads();
    int nn = blockIdx.x * 32 + threadIdx.y;
    int kk = blockIdx.y * 32 + threadIdx.x;
    dstB[(size_t)z * FF + (size_t)nn * FH + kk] = __float2half_rn(t[threadIdx.x][threadIdx.y]);
}
__global__ void wtrans_half(const float* __restrict__ W, __half* __restrict__ Th) {
    __shared__ float t[32][33];
    int k = blockIdx.y * 32 + threadIdx.y;
    int n = blockIdx.x * 32 + threadIdx.x;
    t[threadIdx.y][threadIdx.x] = W[(size_t)k * FH + n];
    __syncthreads();
    int nn = blockIdx.x * 32 + threadIdx.y;
    int kk = blockIdx.y * 32 + threadIdx.x;
    Th[(size_t)nn * FH + kk] = __float2half_rn(t[threadIdx.x][threadIdx.y]);
}
__global__ void bsum_kernel(const float* __restrict__ b, float* __restrict__ bsum) {
    int c = threadIdx.x;
    bsum[c] = b[c] + b[2 * FH + c] + b[3 * FH + c];
}

// ---------------- mma.sync fp16 dual-output multi-part GEMM ----------------
// z = blockIdx.z selects output; C_z[M,512] = sum_p A_zp @ B_zp^T + bias_z.
// CTA tile 128x256, BK=64, 8 warps (2x4), warp tile 64x64, 3-stage cp.async.
// Optional fused BN column stats (sum/sumsq with bias, row-validity-guarded).
struct Gemm2Args {
    const __half* A[2][4];
    const __half* B[2][4];
    int P[2];
    int M[2];
    const float* bias[2];
    float* C[2];
    float* psum;   // nullptr => no stats; else indexed [z*FH + col]
    float* psq;
};

#define BM 128
#define BN 256
#define BK 64
#define STAGES 3
#define SA_SZ 16384
#define SB_SZ 32768
#define STAGE_SZ (SA_SZ + SB_SZ)
#define GEMM_SMEM (STAGES * STAGE_SZ)

__device__ __forceinline__ void gemm_prefetch2(const __half* const* Av, const __half* const* Bv,
                                               int M, int kt, uint32_t sbase, int tid,
                                               int row0, int col0) {
    int part = kt >> 3, kk = kt & 7;
    int stage = kt % STAGES;
    const __half* aP = Av[part];
    const __half* bP = Bv[part];
    int k0 = kk * BK;
    uint32_t sA = sbase + stage * STAGE_SZ;
    uint32_t sB = sA + SA_SZ;
#pragma unroll
    for (int i = 0; i < 4; i++) {
        int idx = tid + i * 256;  // 0..1023
        int r = idx >> 3, ch = idx & 7;
        const __half* g = aP + (size_t)(row0 + r) * FH + k0 + ch * 8;
        uint32_t d = sA + r * 128 + ((ch ^ (r & 7)) << 4);
        int sz = (row0 + r < M) ? 16 : 0;
        CP_ASYNC16(d, g, sz);
    }
#pragma unroll
    for (int i = 0; i < 8; i++) {
        int idx = tid + i * 256;  // 0..2047
        int r = idx >> 3, ch = idx & 7;
        const __half* g = bP + (size_t)(col0 + r) * FH + k0 + ch * 8;
        uint32_t d = sB + r * 128 + ((ch ^ (r & 7)) << 4);
        CP_ASYNC16(d, g, 16);
    }
    CP_COMMIT();
}

__global__ void __launch_bounds__(256) gemm_mma2(Gemm2Args args) {
    extern __shared__ __align__(128) char smem[];
    uint32_t sbase = smem_u32(smem);
    int z = blockIdx.z;
    const __half* const* Av = args.A[z];
    const __half* const* Bv = args.B[z];
    const int P = args.P[z];
    const int M = args.M[z];
    int tid = threadIdx.x;
    int w = tid >> 5, lane = tid & 31;
    int wm = w >> 2, wn = w & 3;
    int row0 = blockIdx.x * BM, col0 = blockIdx.y * BN;

    float c[4][8][4];
#pragma unroll
    for (int mi = 0; mi < 4; mi++)
#pragma unroll
        for (int ni = 0; ni < 8; ni++)
#pragma unroll
            for (int q = 0; q < 4; q++) c[mi][ni][q] = 0.f;

    const int T = P * 8;
    gemm_prefetch2(Av, Bv, M, 0, sbase, tid, row0, col0);
    gemm_prefetch2(Av, Bv, M, 1, sbase, tid, row0, col0);

    for (int kt = 0; kt < T; kt++) {
        CP_WAIT1();
        __syncthreads();
        if (kt + 2 < T)
            gemm_prefetch2(Av, Bv, M, kt + 2, sbase, tid, row0, col0);
        else
            CP_COMMIT();

        int stage = kt % STAGES;
        uint32_t sA = sbase + stage * STAGE_SZ;
        uint32_t sB = sA + SA_SZ;
#pragma unroll
        for (int ks = 0; ks < 4; ks++) {
            int kc0 = ks * 2;
            uint32_t a[4][4];
#pragma unroll
            for (int mi = 0; mi < 4; mi++) {
                int r = wm * 64 + mi * 16 + (lane & 15);
                int ch = kc0 + (lane >> 4);
                uint32_t addr = sA + r * 128 + ((ch ^ (r & 7)) << 4);
                LDSM4(a[mi], addr);
            }
            uint32_t b[4][4];
#pragma unroll
            for (int nb = 0; nb < 4; nb++) {
                int r = wn * 64 + nb * 16 + ((lane >> 3) & 1) * 8 + (lane & 7);
                int ch = kc0 + (lane >> 4);
                uint32_t addr = sB + r * 128 + ((ch ^ (r & 7)) << 4);
                LDSM4(b[nb], addr);
            }
#pragma unroll
            for (int mi = 0; mi < 4; mi++)
#pragma unroll
                for (int ni = 0; ni < 8; ni++) {
                    uint32_t b0 = b[ni >> 1][ni & 1];
                    uint32_t b1 = b[ni >> 1][2 + (ni & 1)];
                    MMA16816(c[mi][ni], a[mi], b0, b1);
                }
        }
    }

    // ---- epilogue: bias + store + optional fused column stats
    int gr = lane >> 2, gc = (lane & 3) * 2;
    float* Cp = args.C[z];
    const float* bias = args.bias[z];
    const bool st = (args.psum != nullptr);

    float2 bv[8];
#pragma unroll
    for (int ni = 0; ni < 8; ni++)
        bv[ni] = *(const float2*)(bias + col0 + wn * 64 + ni * 8 + gc);

    float s[8][2], q[8][2];
#pragma unroll
    for (int ni = 0; ni < 8; ni++) { s[ni][0] = s[ni][1] = q[ni][0] = q[ni][1] = 0.f; }

#pragma unroll
    for (int mi = 0; mi < 4; mi++) {
        int r0 = row0 + wm * 64 + mi * 16 + gr;
        bool v0 = r0 < M, v1 = (r0 + 8) < M;
#pragma unroll
        for (int ni = 0; ni < 8; ni++) {
            int cc = col0 + wn * 64 + ni * 8 + gc;
            float x0 = c[mi][ni][0] + bv[ni].x;
            float x1 = c[mi][ni][1] + bv[ni].y;
            float x2 = c[mi][ni][2] + bv[ni].x;
            float x3 = c[mi][ni][3] + bv[ni].y;
            if (v0) {
                *(float2*)(Cp + (size_t)r0 * FH + cc) = make_float2(x0, x1);
                if (st) {
                    s[ni][0] += x0; s[ni][1] += x1;
                    q[ni][0] += x0 * x0; q[ni][1] += x1 * x1;
                }
            }
            if (v1) {
                *(float2*)(Cp + (size_t)(r0 + 8) * FH + cc) = make_float2(x2, x3);
                if (st) {
                    s[ni][0] += x2; s[ni][1] += x3;
                    q[ni][0] += x2 * x2; q[ni][1] += x3 * x3;
                }
            }
        }
    }

    if (st) {
#pragma unroll
        for (int ni = 0; ni < 8; ni++)
#pragma unroll
            for (int qq = 0; qq < 2; qq++) {
#pragma unroll
                for (int off = 16; off >= 4; off >>= 1) {
                    s[ni][qq] += __shfl_down_sync(0xffffffffu, s[ni][qq], off);
                    q[ni][qq] += __shfl_down_sync(0xffffffffu, q[ni][qq], off);
                }
            }
        if (lane < 4) {
#pragma unroll
            for (int ni = 0; ni < 8; ni++)
#pragma unroll
                for (int qq = 0; qq < 2; qq++) {
                    int cc = col0 + wn * 64 + ni * 8 + lane * 2 + qq;
                    atomicAdd(&args.psum[z * FH + cc], s[ni][qq]);
                    atomicAdd(&args.psq[z * FH + cc], q[ni][qq]);
                }
        }
    }
}

// ---------------- BN finalize + apply ----------------
__global__ void bn_finalize3(const float* __restrict__ psum, const float* __restrict__ psq,
                             const float* __restrict__ gamma, const float* __restrict__ beta,
                             float* __restrict__ scale, float* __restrict__ shift) {
    int z = blockIdx.x;
    int c = threadIdx.x;
    int i = z * FH + c;
    float m = psum[i] / 20000.0f;
    float var = psq[i] / 20000.0f - m * m;
    float rstd = rsqrtf(var + 1e-5f);
    float sc = gamma[i] * rstd;
    scale[i] = sc;
    shift[i] = beta[i] - m * sc;
}
// combined BN+ReLU -> fp16 for both node types
__global__ void bnrelu2(const float* __restrict__ Da, const float* __restrict__ Pa,
                        __half* __restrict__ Hd, __half* __restrict__ Hp,
                        const float* __restrict__ scale, const float* __restrict__ shift) {
    int z = blockIdx.y;
    const float* X = z ? Pa : Da;
    __half* H = z ? Hp : Hd;
    int i = blockIdx.x * blockDim.x + threadIdx.x;
    int total = 20000 * FH / 4;
    if (i >= total) return;
    int c = z * FH + (i & 127) * 4;
    float4 x = ((const float4*)X)[i];
    float4 sc = *(const float4*)(scale + c);
    float4 sh = *(const float4*)(shift + c);
    float y0 = fmaxf(fmaf(x.x, sc.x, sh.x), 0.f);
    float y1 = fmaxf(fmaf(x.y, sc.y, sh.y), 0.f);
    float y2 = fmaxf(fmaf(x.z, sc.z, sh.z), 0.f);
    float y3 = fmaxf(fmaf(x.w, sc.w, sh.w), 0.f);
    __half2 h0 = __floats2half2_rn(y0, y1);
    __half2 h1 = __floats2half2_rn(y2, y3);
    uint2 v;
    v.x = *(const uint32_t*)&h0;
    v.y = *(const uint32_t*)&h1;
    ((uint2*)H)[i] = v;
}

// ---------------- host orchestration ----------------
extern "C" void kernel_launch(void* const* d_in, const int* in_sizes, int n_in,
                              void* d_out, int out_size) {
    const float* h_d = (const float*)d_in[0];
    const float* h_p = (const float*)d_in[1];
    const float* Ws1 = (const float*)d_in[2];
    const float* Wn1 = (const float*)d_in[3];
    const float* b1  = (const float*)d_in[4];
    const float* Ws2 = (const float*)d_in[5];
    const float* Wn2 = (const float*)d_in[6];
    const float* b2  = (const float*)d_in[7];
    const float* bng = (const float*)d_in[8];
    const float* bnb = (const float*)d_in[9];
    const float* pWd = (const float*)d_in[10];
    const float* pbd = (const float*)d_in[11];
    const float* pWp = (const float*)d_in[12];
    const float* pbp = (const float*)d_in[13];
    const int* a_src = (const int*)d_in[14];
    const int* a_dst = (const int*)d_in[15];
    const int* i_src = (const int*)d_in[16];
    const int* i_dst = (const int*)d_in[17];
    float* out = (float*)d_out;

    cudaFuncSetAttribute(gemm_mma2, cudaFuncAttributeMaxDynamicSharedMemorySize, GEMM_SMEM);

    float *Da, *Pa, *bsum, *psum, *psq, *scale, *shift;
    __half *Xdh, *Xph, *MhB, *WthB;
    int *off, *cur, *val;
    cudaGetSymbolAddress((void**)&Da, g_Da);
    cudaGetSymbolAddress((void**)&Pa, g_Pa);
    cudaGetSymbolAddress((void**)&bsum, g_bsum);
    cudaGetSymbolAddress((void**)&psum, g_psum);
    cudaGetSymbolAddress((void**)&psq, g_psq);
    cudaGetSymbolAddress((void**)&scale, g_scale);
    cudaGetSymbolAddress((void**)&shift, g_shift);
    cudaGetSymbolAddress((void**)&Xdh, g_Xdh);
    cudaGetSymbolAddress((void**)&Xph, g_Xph);
    cudaGetSymbolAddress((void**)&MhB, g_Mh);
    cudaGetSymbolAddress((void**)&WthB, g_Wth);
    cudaGetSymbolAddress((void**)&off, g_off);
    cudaGetSymbolAddress((void**)&cur, g_cur);
    cudaGetSymbolAddress((void**)&val, g_val);

    __half *Mh[4], *Wth[6];
    for (int i = 0; i < 4; i++) Mh[i] = MhB + (size_t)i * NN * FH;
    for (int i = 0; i < 6; i++) Wth[i] = WthB + (size_t)i * FF;

    // ---- CSR build: 0:(a_dst<-a_src) 1:(a_src<-a_dst) 2:(i_dst<-i_src) 3:(i_src<-i_dst)
    const int* grps[4] = {a_dst, a_src, i_dst, i_src};
    const int* oths[4] = {a_src, a_dst, i_src, i_dst};
    for (int r = 0; r < 4; r++) {
        int* offr = off + r * (NN + 1);
        int* curr = cur + r * (NN + 1);
        int* valr = val + r * EE;
        cudaMemsetAsync(offr, 0, (NN + 1) * sizeof(int), 0);
        hist_kernel<<<(EE + 255) / 256, 256>>>(grps[r], offr, EE);
        scan_kernel<<<1, 1024>>>(offr, NN);
        cudaMemcpyAsync(curr, offr, (NN + 1) * sizeof(int), cudaMemcpyDeviceToDevice, 0);
        fill_kernel<<<(EE + 255) / 256, 256>>>(grps[r], oths[r], curr, valr, EE);
    }

    // ---- initial activation conversion to fp16
    cvt_half<<<(ND * FH / 4 + 255) / 256, 256>>>(h_d, Xdh, ND * FH / 4);
    cvt_half<<<(NP * FH / 4 + 255) / 256, 256>>>(h_p, Xph, NP * FH / 4);

    dim3 wgrid(16, 16), wblock(32, 32);
    dim3 w6grid(16, 16, 6);
    dim3 ggrid((ND + BM - 1) / BM, FH / BN, 2);
    dim3 sgrid(2048, 4);

    for (int li = 0; li < 2; li++) {
        const float* Ws = li ? Ws2 : Ws1;
        const float* Wn = li ? Wn2 : Wn1;
        const float* bb = li ? b2 : b1;

        wtrans6<<<w6grid, wblock>>>(Ws, Wn, WthB);
        bsum_kernel<<<1, FH>>>(bb, bsum);

        // ---- all 4 segment means in one launch
        {
            SegArgs sa{};
            sa.X[0] = Xdh; sa.off[0] = off + 0 * (NN + 1); sa.val[0] = val + 0 * EE; sa.out[0] = Mh[0];
            sa.X[1] = Xph; sa.off[1] = off + 1 * (NN + 1); sa.val[1] = val + 1 * EE; sa.out[1] = Mh[1];
            sa.X[2] = Xph; sa.off[2] = off + 2 * (NN + 1); sa.val[2] = val + 2 * EE; sa.out[2] = Mh[2];
            sa.X[3] = Xph; sa.off[3] = off + 3 * (NN + 1); sa.val[3] = val + 3 * EE; sa.out[3] = Mh[3];
            seg_mean4<<<sgrid, 128>>>(sa);
        }

        // ---- both SAGE outputs in ONE launch (z=0 disease, z=1 protein), stats fused
        cudaMemsetAsync(psum, 0, 2 * FH * sizeof(float), 0);
        cudaMemsetAsync(psq, 0, 2 * FH * sizeof(float), 0);
        {
            Gemm2Args a{};
            // disease: Xd@Ws1t + mean_r1@Wn1t + b[1]
            a.A[0][0] = Xdh;   a.B[0][0] = Wth[0];
            a.A[0][1] = Mh[1]; a.B[0][1] = Wth[1];
            a.P[0] = 2; a.M[0] = ND; a.bias[0] = bb + FH; a.C[0] = Da;
            // protein: Xp@Wsumt + mean_r0@Wn0t + mean_r2@Wn2t + mean_r3@Wn3t + bsum
            a.A[1][0] = Xph;   a.B[1][0] = Wth[2];
            a.A[1][1] = Mh[0]; a.B[1][1] = Wth[3];
            a.A[1][2] = Mh[2]; a.B[1][2] = Wth[4];
            a.A[1][3] = Mh[3]; a.B[1][3] = Wth[5];
            a.P[1] = 4; a.M[1] = NP; a.bias[1] = bsum; a.C[1] = Pa;
            a.psum = psum; a.psq = psq;
            gemm_mma2<<<ggrid, 256, GEMM_SMEM>>>(a);
        }

        // ---- BN finalize + apply (both node types)
        bn_finalize3<<<2, FH>>>(psum, psq, bng + li * 2 * FH, bnb + li * 2 * FH, scale, shift);
        dim3 bgrid((ND * FH / 4 + 255) / 256, 2);
        bnrelu2<<<bgrid, 256>>>(Da, Pa, Xdh, Xph, scale, shift);
    }

    // ---- final projections, one launch, straight into d_out
    wtrans_half<<<wgrid, wblock>>>(pWd, Wth[0]);
    wtrans_half<<<wgrid, wblock>>>(pWp, Wth[1]);
    {
        Gemm2Args a{};
        a.A[0][0] = Xdh; a.B[0][0] = Wth[0];
        a.P[0] = 1; a.M[0] = ND; a.bias[0] = pbd; a.C[0] = out;
        a.A[1][0] = Xph; a.B[1][0] = Wth[1];
        a.P[1] = 1; a.M[1] = NP; a.bias[1] = pbp; a.C[1] = out + (size_t)ND * FH;
        a.psum = nullptr; a.psq = nullptr;
        gemm_mma2<<<ggrid, 256, GEMM_SMEM>>>(a);
    }
}

// round 15
// speedup vs baseline: 1.6522x; 1.6522x over previous
#include <cuda_runtime.h>
#include <cuda_fp16.h>
#include <cstdint>

#define ND 20000
#define NP 20000
#define NN 20000
#define FH 512
#define FF (FH * FH)
#define EE 320000

// ---------------- device scratch (static, no allocation) ----------------
__device__ float g_Da[ND * FH], g_Pa[NP * FH];
__device__ __align__(16) __half g_Xdh[ND * FH];
__device__ __align__(16) __half g_Xph[NP * FH];
__device__ __align__(16) __half g_Mh[4][NN * FH];
__device__ __align__(16) __half g_Wth[6][FF];
__device__ float g_bsum[FH], g_scale[2 * FH], g_shift[2 * FH];
__device__ float g_psum[2 * FH], g_psq[2 * FH];
__device__ int g_off[4 * (NN + 1)], g_cur[4 * (NN + 1)], g_val[4 * EE];

// ---------------- helpers ----------------
__device__ __forceinline__ uint32_t smem_u32(const void* p) {
    uint32_t a;
    asm("{ .reg .u64 t; cvta.to.shared.u64 t, %1; cvt.u32.u64 %0, t; }" : "=r"(a) : "l"(p));
    return a;
}

#define LDSM4(r, addr) \
    asm volatile("ldmatrix.sync.aligned.m8n8.x4.shared.b16 {%0,%1,%2,%3}, [%4];" \
                 : "=r"((r)[0]), "=r"((r)[1]), "=r"((r)[2]), "=r"((r)[3]) : "r"(addr))

#define MMA16816(c, a, b0, b1) \
    asm volatile("mma.sync.aligned.m16n8k16.row.col.f32.f16.f16.f32 " \
                 "{%0,%1,%2,%3}, {%4,%5,%6,%7}, {%8,%9}, {%0,%1,%2,%3};" \
                 : "+f"((c)[0]), "+f"((c)[1]), "+f"((c)[2]), "+f"((c)[3]) \
                 : "r"((a)[0]), "r"((a)[1]), "r"((a)[2]), "r"((a)[3]), "r"(b0), "r"(b1))

#define CP_ASYNC16(dst, src, sz) \
    asm volatile("cp.async.cg.shared.global [%0], [%1], 16, %2;" :: "r"(dst), "l"(src), "r"(sz) : "memory")
#define CP_COMMIT() asm volatile("cp.async.commit_group;" ::: "memory")
#define CP_WAIT1() asm volatile("cp.async.wait_group 1;" ::: "memory")

// ---------------- CSR build ----------------
__global__ void hist_kernel(const int* __restrict__ grp, int* __restrict__ off, int E) {
    int e = blockIdx.x * blockDim.x + threadIdx.x;
    if (e < E) atomicAdd(&off[grp[e] + 1], 1);
}
__global__ void scan_kernel(int* __restrict__ off, int n) {
    __shared__ int ssum[1024];
    const int T = 1024;
    int t = threadIdx.x;
    int chunk = (n + T - 1) / T;
    int lo = 1 + t * chunk;
    int hi = lo + chunk;
    if (hi > n + 1) hi = n + 1;
    int s = 0;
    for (int i = lo; i < hi && i <= n; i++) s += off[i];
    ssum[t] = s;
    __syncthreads();
    for (int d = 1; d < T; d <<= 1) {
        int v = (t >= d) ? ssum[t - d] : 0;
        __syncthreads();
        ssum[t] += v;
        __syncthreads();
    }
    int run = (t > 0) ? ssum[t - 1] : 0;
    for (int i = lo; i < hi && i <= n; i++) {
        run += off[i];
        off[i] = run;
    }
}
__global__ void fill_kernel(const int* __restrict__ grp, const int* __restrict__ oth,
                            int* __restrict__ cur, int* __restrict__ val, int E) {
    int e = blockIdx.x * blockDim.x + threadIdx.x;
    if (e < E) {
        int p = atomicAdd(&cur[grp[e]], 1);
        val[p] = oth[e];
    }
}

// ---------------- fused 4-relation segment mean (fp16, MLP-unrolled) ----------------
struct SegArgs {
    const __half* X[4];
    const int* off[4];
    const int* val[4];
    __half* out[4];
};
__global__ void seg_mean4(SegArgs args) {
    int rel = blockIdx.y;
    const __half* X = args.X[rel];
    const int* off = args.off[rel];
    const int* val = args.val[rel];
    __half* out = args.out[rel];
    int c = threadIdx.x * 4;  // 128 threads * 4 halves = 512
    for (int d = blockIdx.x; d < NN; d += gridDim.x) {
        int s = off[d], e = off[d + 1];
        float a0 = 0.f, a1 = 0.f, a2 = 0.f, a3 = 0.f;
        int j = s;
        for (; j + 4 <= e; j += 4) {
            int n0 = __ldg(&val[j]);
            int n1 = __ldg(&val[j + 1]);
            int n2 = __ldg(&val[j + 2]);
            int n3 = __ldg(&val[j + 3]);
            uint2 v0 = *(const uint2*)(X + (size_t)n0 * FH + c);
            uint2 v1 = *(const uint2*)(X + (size_t)n1 * FH + c);
            uint2 v2 = *(const uint2*)(X + (size_t)n2 * FH + c);
            uint2 v3 = *(const uint2*)(X + (size_t)n3 * FH + c);
            float2 f;
            f = __half22float2(*(const __half2*)&v0.x); a0 += f.x; a1 += f.y;
            f = __half22float2(*(const __half2*)&v0.y); a2 += f.x; a3 += f.y;
            f = __half22float2(*(const __half2*)&v1.x); a0 += f.x; a1 += f.y;
            f = __half22float2(*(const __half2*)&v1.y); a2 += f.x; a3 += f.y;
            f = __half22float2(*(const __half2*)&v2.x); a0 += f.x; a1 += f.y;
            f = __half22float2(*(const __half2*)&v2.y); a2 += f.x; a3 += f.y;
            f = __half22float2(*(const __half2*)&v3.x); a0 += f.x; a1 += f.y;
            f = __half22float2(*(const __half2*)&v3.y); a2 += f.x; a3 += f.y;
        }
        for (; j < e; j++) {
            int nb = __ldg(&val[j]);
            uint2 v = *(const uint2*)(X + (size_t)nb * FH + c);
            float2 f0 = __half22float2(*(const __half2*)&v.x);
            float2 f1 = __half22float2(*(const __half2*)&v.y);
            a0 += f0.x; a1 += f0.y; a2 += f1.x; a3 += f1.y;
        }
        int deg = e - s;
        float inv = 1.0f / (float)(deg > 0 ? deg : 1);
        __half2 o0 = __floats2half2_rn(a0 * inv, a1 * inv);
        __half2 o1 = __floats2half2_rn(a2 * inv, a3 * inv);
        uint2 ov;
        ov.x = *(const uint32_t*)&o0;
        ov.y = *(const uint32_t*)&o1;
        *(uint2*)(out + (size_t)d * FH + c) = ov;
    }
}

// ---------------- fp32 -> fp16 ----------------
__global__ void cvt_half(const float* __restrict__ X, __half* __restrict__ H, int n4) {
    int i = blockIdx.x * blockDim.x + threadIdx.x;
    if (i >= n4) return;
    float4 x = ((const float4*)X)[i];
    __half2 h0 = __floats2half2_rn(x.x, x.y);
    __half2 h1 = __floats2half2_rn(x.z, x.w);
    uint2 v;
    v.x = *(const uint32_t*)&h0;
    v.y = *(const uint32_t*)&h1;
    ((uint2*)H)[i] = v;
}

// ---------------- fused 6-way weight transpose (+fold for z=2): W[K,N] -> T[N,K] fp16 ----
__global__ void wtrans6(const float* __restrict__ Ws, const float* __restrict__ Wn,
                        __half* __restrict__ dstB) {
    __shared__ float t[32][33];
    int z = blockIdx.z;
    int k = blockIdx.y * 32 + threadIdx.y;
    int n = blockIdx.x * 32 + threadIdx.x;
    size_t idx = (size_t)k * FH + n;
    float v;
    switch (z) {
        case 0: v = Ws[FF + idx]; break;
        case 1: v = Wn[FF + idx]; break;
        case 2: v = Ws[idx] + Ws[2 * FF + idx] + Ws[3 * FF + idx]; break;
        case 3: v = Wn[idx]; break;
        case 4: v = Wn[2 * FF + idx]; break;
        default: v = Wn[3 * FF + idx]; break;
    }
    t[threadIdx.y][threadIdx.x] = v;
    __syncthreads();
    int nn = blockIdx.x * 32 + threadIdx.y;
    int kk = blockIdx.y * 32 + threadIdx.x;
    dstB[(size_t)z * FF + (size_t)nn * FH + kk] = __float2half_rn(t[threadIdx.x][threadIdx.y]);
}
__global__ void wtrans_half(const float* __restrict__ W, __half* __restrict__ Th) {
    __shared__ float t[32][33];
    int k = blockIdx.y * 32 + threadIdx.y;
    int n = blockIdx.x * 32 + threadIdx.x;
    t[threadIdx.y][threadIdx.x] = W[(size_t)k * FH + n];
    __syncthreads();
    int nn = blockIdx.x * 32 + threadIdx.y;
    int kk = blockIdx.y * 32 + threadIdx.x;
    Th[(size_t)nn * FH + kk] = __float2half_rn(t[threadIdx.x][threadIdx.y]);
}
__global__ void bsum_kernel(const float* __restrict__ b, float* __restrict__ bsum) {
    int c = threadIdx.x;
    bsum[c] = b[c] + b[2 * FH + c] + b[3 * FH + c];
}

// ---------------- mma.sync fp16 dual-output multi-part GEMM (R12 tile shape) --------
// z = blockIdx.z selects output; C_z[M,512] = sum_p A_zp @ B_zp^T + bias_z.
// CTA tile 128x128, BK=64, 8 warps (2x4), warp tile 64x32, 3-stage cp.async (96KB).
// Optional fused BN column stats from the exact fp32 accumulators.
struct Gemm2Args {
    const __half* A[2][4];
    const __half* B[2][4];
    int P[2];
    int M[2];
    const float* bias[2];
    float* C[2];
    float* psum;   // nullptr => no stats; else indexed [z*FH + col]
    float* psq;
};

#define BM 128
#define BN 128
#define BK 64
#define STAGES 3
#define STAGE_SZ 32768  // A 16KB + B 16KB
#define GEMM_SMEM (STAGES * STAGE_SZ)

__device__ __forceinline__ void gemm_prefetch2(const __half* const* Av, const __half* const* Bv,
                                               int M, int kt, uint32_t sbase, int tid,
                                               int row0, int col0) {
    int part = kt >> 3, kk = kt & 7;
    int stage = kt % STAGES;
    const __half* aP = Av[part];
    const __half* bP = Bv[part];
    int k0 = kk * BK;
    uint32_t sA = sbase + stage * STAGE_SZ;
    uint32_t sB = sA + 16384;
#pragma unroll
    for (int i = 0; i < 4; i++) {
        int idx = tid + i * 256;  // 0..1023
        int r = idx >> 3, ch = idx & 7;
        const __half* g = aP + (size_t)(row0 + r) * FH + k0 + ch * 8;
        uint32_t d = sA + r * 128 + ((ch ^ (r & 7)) << 4);
        int sz = (row0 + r < M) ? 16 : 0;
        CP_ASYNC16(d, g, sz);
    }
#pragma unroll
    for (int i = 0; i < 4; i++) {
        int idx = tid + i * 256;
        int r = idx >> 3, ch = idx & 7;
        const __half* g = bP + (size_t)(col0 + r) * FH + k0 + ch * 8;
        uint32_t d = sB + r * 128 + ((ch ^ (r & 7)) << 4);
        CP_ASYNC16(d, g, 16);
    }
    CP_COMMIT();
}

__global__ void __launch_bounds__(256) gemm_mma2(Gemm2Args args) {
    extern __shared__ __align__(128) char smem[];
    uint32_t sbase = smem_u32(smem);
    int z = blockIdx.z;
    const __half* const* Av = args.A[z];
    const __half* const* Bv = args.B[z];
    const int P = args.P[z];
    const int M = args.M[z];
    int tid = threadIdx.x;
    int w = tid >> 5, lane = tid & 31;
    int wm = w >> 2, wn = w & 3;
    int row0 = blockIdx.x * BM, col0 = blockIdx.y * BN;

    float c[4][4][4];
#pragma unroll
    for (int mi = 0; mi < 4; mi++)
#pragma unroll
        for (int ni = 0; ni < 4; ni++)
#pragma unroll
            for (int q = 0; q < 4; q++) c[mi][ni][q] = 0.f;

    const int T = P * 8;
    gemm_prefetch2(Av, Bv, M, 0, sbase, tid, row0, col0);
    gemm_prefetch2(Av, Bv, M, 1, sbase, tid, row0, col0);

    for (int kt = 0; kt < T; kt++) {
        CP_WAIT1();
        __syncthreads();
        if (kt + 2 < T)
            gemm_prefetch2(Av, Bv, M, kt + 2, sbase, tid, row0, col0);
        else
            CP_COMMIT();

        int stage = kt % STAGES;
        uint32_t sA = sbase + stage * STAGE_SZ;
        uint32_t sB = sA + 16384;
#pragma unroll
        for (int ks = 0; ks < 4; ks++) {
            int kc0 = ks * 2;
            uint32_t a[4][4];
#pragma unroll
            for (int mi = 0; mi < 4; mi++) {
                int r = wm * 64 + mi * 16 + (lane & 15);
                int ch = kc0 + (lane >> 4);
                uint32_t addr = sA + r * 128 + ((ch ^ (r & 7)) << 4);
                LDSM4(a[mi], addr);
            }
            uint32_t b[2][4];
#pragma unroll
            for (int nb = 0; nb < 2; nb++) {
                int r = wn * 32 + nb * 16 + ((lane >> 3) & 1) * 8 + (lane & 7);
                int ch = kc0 + (lane >> 4);
                uint32_t addr = sB + r * 128 + ((ch ^ (r & 7)) << 4);
                LDSM4(b[nb], addr);
            }
#pragma unroll
            for (int mi = 0; mi < 4; mi++)
#pragma unroll
                for (int ni = 0; ni < 4; ni++) {
                    uint32_t b0 = b[ni >> 1][ni & 1];
                    uint32_t b1 = b[ni >> 1][2 + (ni & 1)];
                    MMA16816(c[mi][ni], a[mi], b0, b1);
                }
        }
    }

    // ---- epilogue: bias + store + optional fused column stats
    int gr = lane >> 2, gc = (lane & 3) * 2;
    float* Cp = args.C[z];
    const float* bias = args.bias[z];
    const bool st = (args.psum != nullptr);

    float2 bv[4];
#pragma unroll
    for (int ni = 0; ni < 4; ni++)
        bv[ni] = *(const float2*)(bias + col0 + wn * 32 + ni * 8 + gc);

    float s[4][2], q[4][2];
#pragma unroll
    for (int ni = 0; ni < 4; ni++) { s[ni][0] = s[ni][1] = q[ni][0] = q[ni][1] = 0.f; }

#pragma unroll
    for (int mi = 0; mi < 4; mi++) {
        int r0 = row0 + wm * 64 + mi * 16 + gr;
        bool v0 = r0 < M, v1 = (r0 + 8) < M;
#pragma unroll
        for (int ni = 0; ni < 4; ni++) {
            int cc = col0 + wn * 32 + ni * 8 + gc;
            float x0 = c[mi][ni][0] + bv[ni].x;
            float x1 = c[mi][ni][1] + bv[ni].y;
            float x2 = c[mi][ni][2] + bv[ni].x;
            float x3 = c[mi][ni][3] + bv[ni].y;
            if (v0) {
                *(float2*)(Cp + (size_t)r0 * FH + cc) = make_float2(x0, x1);
                if (st) {
                    s[ni][0] += x0; s[ni][1] += x1;
                    q[ni][0] += x0 * x0; q[ni][1] += x1 * x1;
                }
            }
            if (v1) {
                *(float2*)(Cp + (size_t)(r0 + 8) * FH + cc) = make_float2(x2, x3);
                if (st) {
                    s[ni][0] += x2; s[ni][1] += x3;
                    q[ni][0] += x2 * x2; q[ni][1] += x3 * x3;
                }
            }
        }
    }

    if (st) {
#pragma unroll
        for (int ni = 0; ni < 4; ni++)
#pragma unroll
            for (int qq = 0; qq < 2; qq++) {
#pragma unroll
                for (int off = 16; off >= 4; off >>= 1) {
                    s[ni][qq] += __shfl_down_sync(0xffffffffu, s[ni][qq], off);
                    q[ni][qq] += __shfl_down_sync(0xffffffffu, q[ni][qq], off);
                }
            }
        if (lane < 4) {
#pragma unroll
            for (int ni = 0; ni < 4; ni++)
#pragma unroll
                for (int qq = 0; qq < 2; qq++) {
                    int cc = col0 + wn * 32 + ni * 8 + lane * 2 + qq;
                    atomicAdd(&args.psum[z * FH + cc], s[ni][qq]);
                    atomicAdd(&args.psq[z * FH + cc], q[ni][qq]);
                }
        }
    }
}

// ---------------- BN finalize + apply ----------------
__global__ void bn_finalize3(const float* __restrict__ psum, const float* __restrict__ psq,
                             const float* __restrict__ gamma, const float* __restrict__ beta,
                             float* __restrict__ scale, float* __restrict__ shift) {
    int z = blockIdx.x;
    int c = threadIdx.x;
    int i = z * FH + c;
    float m = psum[i] / 20000.0f;
    float var = psq[i] / 20000.0f - m * m;
    float rstd = rsqrtf(var + 1e-5f);
    float sc = gamma[i] * rstd;
    scale[i] = sc;
    shift[i] = beta[i] - m * sc;
}
// combined BN+ReLU -> fp16 for both node types
__global__ void bnrelu2(const float* __restrict__ Da, const float* __restrict__ Pa,
                        __half* __restrict__ Hd, __half* __restrict__ Hp,
                        const float* __restrict__ scale, const float* __restrict__ shift) {
    int z = blockIdx.y;
    const float* X = z ? Pa : Da;
    __half* H = z ? Hp : Hd;
    int i = blockIdx.x * blockDim.x + threadIdx.x;
    int total = 20000 * FH / 4;
    if (i >= total) return;
    int c = z * FH + (i & 127) * 4;
    float4 x = ((const float4*)X)[i];
    float4 sc = *(const float4*)(scale + c);
    float4 sh = *(const float4*)(shift + c);
    float y0 = fmaxf(fmaf(x.x, sc.x, sh.x), 0.f);
    float y1 = fmaxf(fmaf(x.y, sc.y, sh.y), 0.f);
    float y2 = fmaxf(fmaf(x.z, sc.z, sh.z), 0.f);
    float y3 = fmaxf(fmaf(x.w, sc.w, sh.w), 0.f);
    __half2 h0 = __floats2half2_rn(y0, y1);
    __half2 h1 = __floats2half2_rn(y2, y3);
    uint2 v;
    v.x = *(const uint32_t*)&h0;
    v.y = *(const uint32_t*)&h1;
    ((uint2*)H)[i] = v;
}

// ---------------- host orchestration ----------------
extern "C" void kernel_launch(void* const* d_in, const int* in_sizes, int n_in,
                              void* d_out, int out_size) {
    const float* h_d = (const float*)d_in[0];
    const float* h_p = (const float*)d_in[1];
    const float* Ws1 = (const float*)d_in[2];
    const float* Wn1 = (const float*)d_in[3];
    const float* b1  = (const float*)d_in[4];
    const float* Ws2 = (const float*)d_in[5];
    const float* Wn2 = (const float*)d_in[6];
    const float* b2  = (const float*)d_in[7];
    const float* bng = (const float*)d_in[8];
    const float* bnb = (const float*)d_in[9];
    const float* pWd = (const float*)d_in[10];
    const float* pbd = (const float*)d_in[11];
    const float* pWp = (const float*)d_in[12];
    const float* pbp = (const float*)d_in[13];
    const int* a_src = (const int*)d_in[14];
    const int* a_dst = (const int*)d_in[15];
    const int* i_src = (const int*)d_in[16];
    const int* i_dst = (const int*)d_in[17];
    float* out = (float*)d_out;

    cudaFuncSetAttribute(gemm_mma2, cudaFuncAttributeMaxDynamicSharedMemorySize, GEMM_SMEM);

    float *Da, *Pa, *bsum, *psum, *psq, *scale, *shift;
    __half *Xdh, *Xph, *MhB, *WthB;
    int *off, *cur, *val;
    cudaGetSymbolAddress((void**)&Da, g_Da);
    cudaGetSymbolAddress((void**)&Pa, g_Pa);
    cudaGetSymbolAddress((void**)&bsum, g_bsum);
    cudaGetSymbolAddress((void**)&psum, g_psum);
    cudaGetSymbolAddress((void**)&psq, g_psq);
    cudaGetSymbolAddress((void**)&scale, g_scale);
    cudaGetSymbolAddress((void**)&shift, g_shift);
    cudaGetSymbolAddress((void**)&Xdh, g_Xdh);
    cudaGetSymbolAddress((void**)&Xph, g_Xph);
    cudaGetSymbolAddress((void**)&MhB, g_Mh);
    cudaGetSymbolAddress((void**)&WthB, g_Wth);
    cudaGetSymbolAddress((void**)&off, g_off);
    cudaGetSymbolAddress((void**)&cur, g_cur);
    cudaGetSymbolAddress((void**)&val, g_val);

    __half *Mh[4], *Wth[6];
    for (int i = 0; i < 4; i++) Mh[i] = MhB + (size_t)i * NN * FH;
    for (int i = 0; i < 6; i++) Wth[i] = WthB + (size_t)i * FF;

    // ---- CSR build: 0:(a_dst<-a_src) 1:(a_src<-a_dst) 2:(i_dst<-i_src) 3:(i_src<-i_dst)
    const int* grps[4] = {a_dst, a_src, i_dst, i_src};
    const int* oths[4] = {a_src, a_dst, i_src, i_dst};
    for (int r = 0; r < 4; r++) {
        int* offr = off + r * (NN + 1);
        int* curr = cur + r * (NN + 1);
        int* valr = val + r * EE;
        cudaMemsetAsync(offr, 0, (NN + 1) * sizeof(int), 0);
        hist_kernel<<<(EE + 255) / 256, 256>>>(grps[r], offr, EE);
        scan_kernel<<<1, 1024>>>(offr, NN);
        cudaMemcpyAsync(curr, offr, (NN + 1) * sizeof(int), cudaMemcpyDeviceToDevice, 0);
        fill_kernel<<<(EE + 255) / 256, 256>>>(grps[r], oths[r], curr, valr, EE);
    }

    // ---- initial activation conversion to fp16
    cvt_half<<<(ND * FH / 4 + 255) / 256, 256>>>(h_d, Xdh, ND * FH / 4);
    cvt_half<<<(NP * FH / 4 + 255) / 256, 256>>>(h_p, Xph, NP * FH / 4);

    dim3 wgrid(16, 16), wblock(32, 32);
    dim3 w6grid(16, 16, 6);
    dim3 ggrid((ND + BM - 1) / BM, FH / BN, 2);
    dim3 sgrid(2048, 4);

    for (int li = 0; li < 2; li++) {
        const float* Ws = li ? Ws2 : Ws1;
        const float* Wn = li ? Wn2 : Wn1;
        const float* bb = li ? b2 : b1;

        wtrans6<<<w6grid, wblock>>>(Ws, Wn, WthB);
        bsum_kernel<<<1, FH>>>(bb, bsum);

        // ---- all 4 segment means in one launch
        {
            SegArgs sa{};
            sa.X[0] = Xdh; sa.off[0] = off + 0 * (NN + 1); sa.val[0] = val + 0 * EE; sa.out[0] = Mh[0];
            sa.X[1] = Xph; sa.off[1] = off + 1 * (NN + 1); sa.val[1] = val + 1 * EE; sa.out[1] = Mh[1];
            sa.X[2] = Xph; sa.off[2] = off + 2 * (NN + 1); sa.val[2] = val + 2 * EE; sa.out[2] = Mh[2];
            sa.X[3] = Xph; sa.off[3] = off + 3 * (NN + 1); sa.val[3] = val + 3 * EE; sa.out[3] = Mh[3];
            seg_mean4<<<sgrid, 128>>>(sa);
        }

        // ---- both SAGE outputs in ONE launch (z=0 disease, z=1 protein), stats fused
        cudaMemsetAsync(psum, 0, 2 * FH * sizeof(float), 0);
        cudaMemsetAsync(psq, 0, 2 * FH * sizeof(float), 0);
        {
            Gemm2Args a{};
            // disease: Xd@Ws1t + mean_r1@Wn1t + b[1]
            a.A[0][0] = Xdh;   a.B[0][0] = Wth[0];
            a.A[0][1] = Mh[1]; a.B[0][1] = Wth[1];
            a.P[0] = 2; a.M[0] = ND; a.bias[0] = bb + FH; a.C[0] = Da;
            // protein: Xp@Wsumt + mean_r0@Wn0t + mean_r2@Wn2t + mean_r3@Wn3t + bsum
            a.A[1][0] = Xph;   a.B[1][0] = Wth[2];
            a.A[1][1] = Mh[0]; a.B[1][1] = Wth[3];
            a.A[1][2] = Mh[2]; a.B[1][2] = Wth[4];
            a.A[1][3] = Mh[3]; a.B[1][3] = Wth[5];
            a.P[1] = 4; a.M[1] = NP; a.bias[1] = bsum; a.C[1] = Pa;
            a.psum = psum; a.psq = psq;
            gemm_mma2<<<ggrid, 256, GEMM_SMEM>>>(a);
        }

        // ---- BN finalize + apply (both node types)
        bn_finalize3<<<2, FH>>>(psum, psq, bng + li * 2 * FH, bnb + li * 2 * FH, scale, shift);
        dim3 bgrid((ND * FH / 4 + 255) / 256, 2);
        bnrelu2<<<bgrid, 256>>>(Da, Pa, Xdh, Xph, scale, shift);
    }

    // ---- final projections, one launch, straight into d_out
    wtrans_half<<<wgrid, wblock>>>(pWd, Wth[0]);
    wtrans_half<<<wgrid, wblock>>>(pWp, Wth[1]);
    {
        Gemm2Args a{};
        a.A[0][0] = Xdh; a.B[0][0] = Wth[0];
        a.P[0] = 1; a.M[0] = ND; a.bias[0] = pbd; a.C[0] = out;
        a.A[1][0] = Xph; a.B[1][0] = Wth[1];
        a.P[1] = 1; a.M[1] = NP; a.bias[1] = pbp; a.C[1] = out + (size_t)ND * FH;
        a.psum = nullptr; a.psq = nullptr;
        gemm_mma2<<<ggrid, 256, GEMM_SMEM>>>(a);
    }
}